// round 7
// baseline (speedup 1.0000x reference)
#include <cuda_runtime.h>
#include <math.h>

// Problem constants
#define BB    32
#define CIN   64
#define HIN   128
#define WINP  128
#define COUTT 128
#define OHH   126
#define OWW   126

// Tiling
#define TILE_OH 16
#define TILE_OW 32
#define TILE_CO 32
#define CK      8     // cin chunk

// Block: 256 threads.
//   tc   = tid>>6  in [0,4)   -> cout sub-tile of 8 (co0 + tc*8 + 0..7)
//   tp   = tid&63
//   trow = tp>>2   in [0,16)  -> output row within tile
//   tcg  = tp&3    in [0,4)   -> 8-wide column group
// Each thread: acc[8 couts][8 cols] register tile (64 FMAs per weight-octet).

__global__ __launch_bounds__(256, 2)
void conv3x3_fused_kernel(const float* __restrict__ x,
                          const float* __restrict__ w,
                          const float* __restrict__ bias,
                          const float* __restrict__ mult,
                          float* __restrict__ out)
{
    // stride 35 (odd) -> verified conflict-free for the (row, colgroup) access set
    __shared__ float sx[CK][TILE_OH + 2][TILE_OW + 3];
    __shared__ float sw[CK][3][3][TILE_CO];

    const int tid  = threadIdx.x;
    const int tc   = tid >> 6;
    const int tp   = tid & 63;
    const int trow = tp >> 2;
    const int tcg  = tp & 3;

    const int ow_base = blockIdx.x * TILE_OW;
    const int oh_base = blockIdx.y * TILE_OH;
    const int b       = blockIdx.z >> 2;
    const int co0     = (blockIdx.z & 3) * TILE_CO;

    float acc[8][8];
#pragma unroll
    for (int i = 0; i < 8; i++)
#pragma unroll
        for (int j = 0; j < 8; j++) acc[i][j] = 0.f;

    for (int ci0 = 0; ci0 < CIN; ci0 += CK) {
        // ---- load input tile (CK x 18 x 34), zero-padded at image edges ----
        for (int idx = tid; idx < CK * (TILE_OH + 2) * (TILE_OW + 2); idx += 256) {
            int c  = idx % (TILE_OW + 2);
            int t  = idx / (TILE_OW + 2);
            int r  = t % (TILE_OH + 2);
            int ck = t / (TILE_OH + 2);
            int gh = oh_base + r;
            int gw = ow_base + c;
            float v = 0.f;
            if (gh < HIN && gw < WINP)
                v = x[(((size_t)b * CIN + ci0 + ck) * HIN + gh) * WINP + gw];
            sx[ck][r][c] = v;
        }
        // ---- load weights (CK x 3 x 3 x 32 couts) ----
        for (int idx = tid; idx < CK * 9 * TILE_CO; idx += 256) {
            int co = idx & 31;
            int t  = idx >> 5;
            int kk = t % 9;
            int ck = t / 9;
            sw[ck][kk / 3][kk % 3][co] =
                w[((size_t)(co0 + co) * CIN + ci0 + ck) * 9 + kk];
        }
        __syncthreads();

#pragma unroll 2
        for (int ck = 0; ck < CK; ck++) {
#pragma unroll
            for (int ki = 0; ki < 3; ki++) {
                // 10-wide sliding window covers all three kj shifts
                float win[10];
#pragma unroll
                for (int j = 0; j < 10; j++)
                    win[j] = sx[ck][trow + ki][tcg * 8 + j];
#pragma unroll
                for (int kj = 0; kj < 3; kj++) {
                    float4 w0 = *reinterpret_cast<const float4*>(&sw[ck][ki][kj][tc * 8]);
                    float4 w1 = *reinterpret_cast<const float4*>(&sw[ck][ki][kj][tc * 8 + 4]);
                    float wv[8] = {w0.x, w0.y, w0.z, w0.w, w1.x, w1.y, w1.z, w1.w};
#pragma unroll
                    for (int i = 0; i < 8; i++)
#pragma unroll
                        for (int j = 0; j < 8; j++)
                            acc[i][j] = fmaf(wv[i], win[j + kj], acc[i][j]);
                }
            }
        }
        __syncthreads();
    }

    // ---- fused epilogue: bias -> multiplier -> leaky relu -> tanh-GELU ----
    const int   oh = oh_base + trow;
    const float c0 = 0.7978845608028654f;  // sqrt(2/pi)
#pragma unroll
    for (int i = 0; i < 8; i++) {
        const int   co = co0 + tc * 8 + i;
        const float bi = bias[co];
        const float mu = mult[co];
#pragma unroll
        for (int j = 0; j < 8; j++) {
            const int ow = ow_base + tcg * 8 + j;
            float y = (acc[i][j] + bi) * mu;
            y = (y >= 0.f) ? y : 0.01f * y;
            float t = c0 * (y + 0.044715f * y * y * y);
            float g = 0.5f * y * (1.f + tanhf(t));
            if (oh < OHH && ow < OWW)
                out[(((size_t)b * COUTT + co) * OHH + oh) * OWW + ow] = g;
        }
    }
}

extern "C" void kernel_launch(void* const* d_in, const int* in_sizes, int n_in,
                              void* d_out, int out_size)
{
    const float* x    = (const float*)d_in[0];
    const float* w    = (const float*)d_in[1];
    const float* bias = (const float*)d_in[2];
    const float* mult = (const float*)d_in[3];
    float*       out  = (float*)d_out;

    dim3 grid((OWW + TILE_OW - 1) / TILE_OW,   // 4
              (OHH + TILE_OH - 1) / TILE_OH,   // 8
              BB * 4);                         // 32 batches x 4 cout chunks
    conv3x3_fused_kernel<<<grid, 256>>>(x, w, bias, mult, out);
}

// round 10
// speedup vs baseline: 3.7612x; 3.7612x over previous
#include <cuda_runtime.h>
#include <cstdint>

// ---------------- problem constants ----------------
#define BB    32
#define CIN   64
#define HH    128
#define WW    128
#define COUT  128
#define OHH   126
#define OWW   126

#define NCHUNK 18              // 9 taps x 2 ci-halves, K=32 each
#define ASTRIDE 36             // floats per smem row (conflict-free)
#define TILEF  (128 * ASTRIDE) // 4608 floats per operand tile
#define BUFF   (2 * TILEF)     // A + B per stage
#define SMEMB  (2 * BUFF * 4)  // 73728 bytes, double buffered

// static scratch (allocation-free rule)
__device__ __align__(16) float g_xT[(size_t)BB*HH*WW*CIN + 4096]; // [b][h][w][ci], tf32-rounded
__device__ __align__(16) float g_w2[9*COUT*CIN];                  // [kk][co][ci], tf32-rounded

// ---------------- helpers ----------------
__device__ __forceinline__ uint32_t smem_u32(const void* p) {
    uint32_t a;
    asm("{ .reg .u64 t; cvta.to.shared.u64 t, %1; cvt.u32.u64 %0, t; }" : "=r"(a) : "l"(p));
    return a;
}
__device__ __forceinline__ float f2tf32f(float f) {
    uint32_t r; asm("cvt.rna.tf32.f32 %0, %1;" : "=r"(r) : "f"(f));
    return __uint_as_float(r);
}
__device__ __forceinline__ void cp16(uint32_t s, const void* g) {
    asm volatile("cp.async.cg.shared.global [%0], [%1], 16;" :: "r"(s), "l"(g));
}
__device__ __forceinline__ void mma_tf32(float* d, const float* a, const float* b) {
    asm volatile(
        "mma.sync.aligned.m16n8k8.row.col.f32.tf32.tf32.f32 "
        "{%0,%1,%2,%3}, {%4,%5,%6,%7}, {%8,%9}, {%0,%1,%2,%3};"
        : "+f"(d[0]), "+f"(d[1]), "+f"(d[2]), "+f"(d[3])
        : "r"(__float_as_uint(a[0])), "r"(__float_as_uint(a[1])),
          "r"(__float_as_uint(a[2])), "r"(__float_as_uint(a[3])),
          "r"(__float_as_uint(b[0])), "r"(__float_as_uint(b[1])));
}

// ---------------- pre-pass: w[co][ci][3][3] -> g_w2[kk][co][ci] (tf32) ----------------
__global__ void wtrans_kernel(const float* __restrict__ w) {
    int idx = blockIdx.x * 256 + threadIdx.x;
    if (idx >= 9 * COUT * CIN) return;
    int ci = idx & 63; int t = idx >> 6; int co = t & 127; int kk = t >> 7;
    g_w2[((size_t)kk * COUT + co) * CIN + ci] = f2tf32f(w[((size_t)co * CIN + ci) * 9 + kk]);
}

// ---------------- pre-pass: x[b][ci][h][w] -> g_xT[b][h][w][ci] (tf32) ----------------
__global__ void xtrans_kernel(const float* __restrict__ x) {
    __shared__ float tile[32][33];
    int bh = blockIdx.z;                    // b*128 + h
    int c0 = blockIdx.y * 32;
    int w0 = blockIdx.x * 32;
    int b = bh >> 7, h = bh & 127;
    int tx = threadIdx.x, ty = threadIdx.y; // 32 x 8
    const float* xp = x + ((size_t)b * CIN) * HH * WW + (size_t)h * WW;
#pragma unroll
    for (int i = 0; i < 32; i += 8)
        tile[ty + i][tx] = xp[(size_t)(c0 + ty + i) * HH * WW + w0 + tx];
    __syncthreads();
    float* xo = g_xT + (((size_t)b * HH + h) * WW) * CIN;
#pragma unroll
    for (int i = 0; i < 32; i += 8)
        xo[(size_t)(w0 + ty + i) * CIN + c0 + tx] = f2tf32f(tile[tx][ty + i]);
}

// ---------------- fused activation: bias -> mult -> leaky relu -> tanh GELU ----------------
// tanh via u = e^{-2a}: th = (1-u)/(1+u).  MUFU EX2 + MUFU RCP (__fdividef) —
// ~2 MUFU warp-ops per element, ~30us chip-wide, accuracy ~1e-6 (<< tf32 noise).
__device__ __forceinline__ float actf(float v, float bi, float mu) {
    float y = (v + bi) * mu;
    y = (y >= 0.f) ? y : 0.01f * y;
    float t = 0.7978845608028654f * fmaf(0.044715f * y, y * y, y);
    float a = fminf(fabsf(t), 14.f);
    float u = __expf(-2.f * a);                  // in (0, 1]
    float th = __fdividef(1.f - u, 1.f + u);     // tanh(a), denom in [1,2]
    th = (t >= 0.f) ? th : -th;
    return 0.5f * y * (1.f + th);
}

// ---------------- main kernel: implicit GEMM via mma.sync tf32 ----------------
// CTA = (oh, b). D[co=128][px=128] ; 8 warps in 4(M) x 2(N), each 32x64.
__global__ __launch_bounds__(256, 2)
void conv_mma_kernel(const float* __restrict__ bias, const float* __restrict__ mult,
                     float* __restrict__ out)
{
    extern __shared__ float sm[];
    const int tid = threadIdx.x;
    const int wid = tid >> 5, lid = tid & 31;
    const int wm  = wid >> 1, wn = wid & 1;
    const int g   = lid >> 2, c = lid & 3;
    const int oh  = blockIdx.x;
    const int b   = blockIdx.y;
    const uint32_t sb = smem_u32(sm);

    float acc[2][8][4];
#pragma unroll
    for (int mt = 0; mt < 2; mt++)
#pragma unroll
        for (int nt = 0; nt < 8; nt++)
#pragma unroll
            for (int i = 0; i < 4; i++) acc[mt][nt][i] = 0.f;

#define PREFETCH(CH, BUF) do {                                               \
        const int kk_ = (CH) >> 1, c2_ = (CH) & 1;                           \
        const int ki_ = kk_ / 3, kj_ = kk_ - ki_ * 3;                        \
        const float* wsrc = g_w2 + (size_t)kk_ * COUT * CIN + c2_ * 32;      \
        const float* xsrc = g_xT +                                           \
            ((((size_t)b * HH + oh + ki_) * WW) + kj_) * CIN + c2_ * 32;     \
        const uint32_t ab = sb + (BUF) * (BUFF * 4);                         \
        const uint32_t bb = ab + TILEF * 4;                                  \
        _Pragma("unroll")                                                    \
        for (int kq = 0; kq < 8; kq++) {                                     \
            int idx = tid + kq * 256;                                        \
            int row = (idx >> 3) & 127, k4 = idx & 7;                        \
            if (idx < 1024)                                                  \
                cp16(ab + row * (ASTRIDE * 4) + k4 * 16, wsrc + row * 64 + k4 * 4); \
            else                                                             \
                cp16(bb + row * (ASTRIDE * 4) + k4 * 16, xsrc + (size_t)row * 64 + k4 * 4); \
        }                                                                    \
        asm volatile("cp.async.commit_group;" ::: "memory");                 \
    } while (0)

    PREFETCH(0, 0);

    for (int ch = 0; ch < NCHUNK; ch++) {
        if (ch + 1 < NCHUNK) PREFETCH(ch + 1, (ch + 1) & 1);
        if (ch + 1 < NCHUNK) asm volatile("cp.async.wait_group 1;" ::: "memory");
        else                 asm volatile("cp.async.wait_group 0;" ::: "memory");
        __syncthreads();

        const float* As = sm + (ch & 1) * BUFF;
        const float* Bs = As + TILEF;

#pragma unroll
        for (int ks = 0; ks < 4; ks++) {
            float af[2][4];
#pragma unroll
            for (int mt = 0; mt < 2; mt++) {
                int r = wm * 32 + mt * 16 + g;
                int col = ks * 8 + c;
                af[mt][0] = As[r * ASTRIDE + col];
                af[mt][1] = As[(r + 8) * ASTRIDE + col];
                af[mt][2] = As[r * ASTRIDE + col + 4];
                af[mt][3] = As[(r + 8) * ASTRIDE + col + 4];
            }
            float bf[8][2];
#pragma unroll
            for (int nt = 0; nt < 8; nt++) {
                int n = wn * 64 + nt * 8 + g;
                int k = ks * 8 + c;
                bf[nt][0] = Bs[n * ASTRIDE + k];
                bf[nt][1] = Bs[n * ASTRIDE + k + 4];
            }
#pragma unroll
            for (int mt = 0; mt < 2; mt++)
#pragma unroll
                for (int nt = 0; nt < 8; nt++)
                    mma_tf32(acc[mt][nt], af[mt], bf[nt]);
        }
        __syncthreads();
    }

    // ---- epilogue ----
#pragma unroll
    for (int mt = 0; mt < 2; mt++) {
#pragma unroll
        for (int half = 0; half < 2; half++) {
            const int co = wm * 32 + mt * 16 + g + half * 8;
            const float bi = bias[co];
            const float mu = mult[co];
            float* op = out + (((size_t)b * COUT + co) * OHH + oh) * OWW;
#pragma unroll
            for (int nt = 0; nt < 8; nt++) {
                const int ow = wn * 64 + nt * 8 + 2 * c;
                if (ow + 1 < OWW) {
                    float f0 = actf(acc[mt][nt][half * 2 + 0], bi, mu);
                    float f1 = actf(acc[mt][nt][half * 2 + 1], bi, mu);
                    *reinterpret_cast<float2*>(op + ow) = make_float2(f0, f1);
                }
            }
        }
    }
}

// ---------------- launch ----------------
extern "C" void kernel_launch(void* const* d_in, const int* in_sizes, int n_in,
                              void* d_out, int out_size)
{
    const float* x    = (const float*)d_in[0];
    const float* w    = (const float*)d_in[1];
    const float* bias = (const float*)d_in[2];
    const float* mult = (const float*)d_in[3];
    float*       out  = (float*)d_out;

    cudaFuncSetAttribute(conv_mma_kernel,
                         cudaFuncAttributeMaxDynamicSharedMemorySize, SMEMB);

    wtrans_kernel<<<(9 * COUT * CIN + 255) / 256, 256>>>(w);
    xtrans_kernel<<<dim3(WW / 32, CIN / 32, BB * HH), dim3(32, 8)>>>(x);
    conv_mma_kernel<<<dim3(OHH, BB), 256, SMEMB>>>(bias, mult, out);
}

// round 11
// speedup vs baseline: 5.4590x; 1.4514x over previous
#include <cuda_runtime.h>
#include <cuda_fp16.h>
#include <cstdint>

// ---------------- problem constants ----------------
#define BB    32
#define CIN   64
#define HH    128
#define WW    128
#define COUT  128
#define OHH   126
#define OWW   126

#define NCHUNK 18                // 9 taps x 2 ci-halves, K=32 each
#define TILE_BYTES 8192          // 128 rows x 32 halves (64B rows)
#define STAGE_BYTES (2*TILE_BYTES)
#define SMEMB (2*STAGE_BYTES)    // 32 KB double-buffered

// static scratch (allocation-free rule); fp16, k-interleaved for fragment loads
__device__ __align__(16) __half g_xTh[(size_t)BB*HH*WW*CIN + 8192]; // [b][h][w][perm(ci)]
__device__ __align__(16) __half g_w2h[9*COUT*CIN];                  // [kk][co][perm(ci)]

// ---------------- helpers ----------------
__device__ __forceinline__ uint32_t smem_u32(const void* p) {
    uint32_t a;
    asm("{ .reg .u64 t; cvta.to.shared.u64 t, %1; cvt.u32.u64 %0, t; }" : "=r"(a) : "l"(p));
    return a;
}
__device__ __forceinline__ void cp16(uint32_t s, const void* g) {
    asm volatile("cp.async.cg.shared.global [%0], [%1], 16;" :: "r"(s), "l"(g));
}
// k-interleave within a 16-group: order [0,1,8,9, 2,3,10,11, 4,5,12,13, 6,7,14,15]
__device__ __forceinline__ int permk(int k) {
    return (((k >> 1) & 3) << 2) | (((k >> 3) & 1) << 1) | (k & 1);
}
__device__ __forceinline__ void mma_f16(float* d, const uint32_t* a, const uint32_t* b) {
    asm volatile(
        "mma.sync.aligned.m16n8k16.row.col.f32.f16.f16.f32 "
        "{%0,%1,%2,%3}, {%4,%5,%6,%7}, {%8,%9}, {%0,%1,%2,%3};"
        : "+f"(d[0]), "+f"(d[1]), "+f"(d[2]), "+f"(d[3])
        : "r"(a[0]), "r"(a[1]), "r"(a[2]), "r"(a[3]), "r"(b[0]), "r"(b[1]));
}

// ---------------- pre-pass: w[co][ci][3][3] -> g_w2h[kk][co][perm(ci)] ----------------
__global__ void wtrans_kernel(const float* __restrict__ w) {
    int idx = blockIdx.x * 256 + threadIdx.x;
    if (idx >= 9 * COUT * CIN) return;
    int ci = idx & 63; int t = idx >> 6; int co = t & 127; int kk = t >> 7;
    int q = (ci & ~15) | permk(ci & 15);
    g_w2h[((size_t)kk * COUT + co) * CIN + q] =
        __float2half_rn(w[((size_t)co * CIN + ci) * 9 + kk]);
}

// ---------------- pre-pass: x[b][ci][h][w] -> g_xTh[b][h][w][perm(ci)] ----------------
__global__ void xtrans_kernel(const float* __restrict__ x) {
    __shared__ float tile[32][33];
    int bh = blockIdx.z;                    // b*128 + h
    int c0 = blockIdx.y * 32;
    int w0 = blockIdx.x * 32;
    int b = bh >> 7, h = bh & 127;
    int tx = threadIdx.x, ty = threadIdx.y; // 32 x 8
    const float* xp = x + ((size_t)b * CIN) * HH * WW + (size_t)h * WW;
#pragma unroll
    for (int i = 0; i < 32; i += 8)
        tile[ty + i][tx] = xp[(size_t)(c0 + ty + i) * HH * WW + w0 + tx];
    __syncthreads();
    __half* xo = g_xTh + (((size_t)b * HH + h) * WW) * CIN;
    int ci = c0 + tx;
    int q = (ci & ~15) | permk(ci & 15);
#pragma unroll
    for (int i = 0; i < 32; i += 8)
        xo[(size_t)(w0 + ty + i) * CIN + q] = __float2half_rn(tile[tx][ty + i]);
}

// ---------------- fused activation ----------------
__device__ __forceinline__ float actf(float v, float bi, float mu) {
    float y = (v + bi) * mu;
    y = (y >= 0.f) ? y : 0.01f * y;
    float t = 0.7978845608028654f * fmaf(0.044715f * y, y * y, y);
    float a = fminf(fabsf(t), 14.f);
    float u = __expf(-2.f * a);                  // (0, 1]
    float th = __fdividef(1.f - u, 1.f + u);     // tanh(a)
    th = (t >= 0.f) ? th : -th;
    return 0.5f * y * (1.f + th);
}

// ---------------- main kernel: implicit GEMM via mma.sync f16 ----------------
// CTA = (oh, b). D[co=128][px=128]; 8 warps in 4(M) x 2(N), each 32x64.
__global__ __launch_bounds__(256, 2)
void conv_mma_kernel(const float* __restrict__ bias, const float* __restrict__ mult,
                     float* __restrict__ out)
{
    extern __shared__ char sm[];
    const int tid = threadIdx.x;
    const int wid = tid >> 5, lid = tid & 31;
    const int wm  = wid >> 1, wn = wid & 1;
    const int g   = lid >> 2, c = lid & 3;
    const int oh  = blockIdx.x;
    const int b   = blockIdx.y;
    const uint32_t sb = smem_u32(sm);

    float acc[2][8][4];
#pragma unroll
    for (int mt = 0; mt < 2; mt++)
#pragma unroll
        for (int nt = 0; nt < 8; nt++)
#pragma unroll
            for (int i = 0; i < 4; i++) acc[mt][nt][i] = 0.f;

    // chunk tiles: A 128co x 32k halves (64B rows), B 128px x 32k halves.
    // 16B-block rotation (blk+row)&3 keeps LDS.64 fragment loads conflict-free.
#define PREFETCH(CH, BUF) do {                                                  \
        const int kk_ = (CH) >> 1, c2_ = (CH) & 1;                              \
        const int ki_ = kk_ / 3, kj_ = kk_ - ki_ * 3;                           \
        const __half* wsrc = g_w2h + (size_t)kk_ * COUT * CIN + c2_ * 32;       \
        const __half* xsrc = g_xTh +                                            \
            ((((size_t)b * HH + oh + ki_) * WW) + kj_) * CIN + c2_ * 32;        \
        const uint32_t ab = sb + (BUF) * STAGE_BYTES;                           \
        const uint32_t bb = ab + TILE_BYTES;                                    \
        _Pragma("unroll")                                                       \
        for (int kq = 0; kq < 4; kq++) {                                        \
            int idx = tid + kq * 256;                                           \
            if (idx < 512) {                                                    \
                int row = idx >> 2, blk = idx & 3;                              \
                cp16(ab + row * 64 + (((blk) + row) & 3) * 16,                  \
                     wsrc + (size_t)row * CIN + blk * 8);                       \
            } else {                                                            \
                int j = idx - 512, p = j >> 2, blk = j & 3;                     \
                cp16(bb + p * 64 + (((blk) + p) & 3) * 16,                      \
                     xsrc + (size_t)p * CIN + blk * 8);                         \
            }                                                                   \
        }                                                                       \
        asm volatile("cp.async.commit_group;" ::: "memory");                    \
    } while (0)

    PREFETCH(0, 0);

    for (int ch = 0; ch < NCHUNK; ch++) {
        if (ch + 1 < NCHUNK) {
            PREFETCH(ch + 1, (ch + 1) & 1);
            asm volatile("cp.async.wait_group 1;" ::: "memory");
        } else {
            asm volatile("cp.async.wait_group 0;" ::: "memory");
        }
        __syncthreads();

        const uint32_t Ab = sb + (ch & 1) * STAGE_BYTES;
        const uint32_t Bb = Ab + TILE_BYTES;
        const int s8 = (c & 1) * 8;

#pragma unroll
        for (int ks = 0; ks < 2; ks++) {
            const int blk = ks * 2 + (c >> 1);
            uint32_t af[2][4];
#pragma unroll
            for (int mt = 0; mt < 2; mt++) {
                int r0 = wm * 32 + mt * 16 + g;
                uint32_t a0 = Ab + r0 * 64 + ((blk + r0) & 3) * 16 + s8;
                uint32_t a1 = Ab + (r0 + 8) * 64 + ((blk + r0 + 8) & 3) * 16 + s8;
                asm volatile("ld.shared.v2.b32 {%0,%1}, [%2];"
                             : "=r"(af[mt][0]), "=r"(af[mt][2]) : "r"(a0));
                asm volatile("ld.shared.v2.b32 {%0,%1}, [%2];"
                             : "=r"(af[mt][1]), "=r"(af[mt][3]) : "r"(a1));
            }
            uint32_t bf[8][2];
#pragma unroll
            for (int nt = 0; nt < 8; nt++) {
                int n = wn * 64 + nt * 8 + g;
                uint32_t a = Bb + n * 64 + ((blk + n) & 3) * 16 + s8;
                asm volatile("ld.shared.v2.b32 {%0,%1}, [%2];"
                             : "=r"(bf[nt][0]), "=r"(bf[nt][1]) : "r"(a));
            }
#pragma unroll
            for (int mt = 0; mt < 2; mt++)
#pragma unroll
                for (int nt = 0; nt < 8; nt++)
                    mma_f16(acc[mt][nt], af[mt], bf[nt]);
        }
        __syncthreads();
    }

    // ---- epilogue: bias -> mult -> leaky -> GELU -> store ----
#pragma unroll
    for (int mt = 0; mt < 2; mt++) {
#pragma unroll
        for (int half = 0; half < 2; half++) {
            const int co = wm * 32 + mt * 16 + g + half * 8;
            const float bi = bias[co];
            const float mu = mult[co];
            float* op = out + (((size_t)b * COUT + co) * OHH + oh) * OWW;
#pragma unroll
            for (int nt = 0; nt < 8; nt++) {
                const int ow = wn * 64 + nt * 8 + 2 * c;
                if (ow + 1 < OWW) {
                    float f0 = actf(acc[mt][nt][half * 2 + 0], bi, mu);
                    float f1 = actf(acc[mt][nt][half * 2 + 1], bi, mu);
                    *reinterpret_cast<float2*>(op + ow) = make_float2(f0, f1);
                }
            }
        }
    }
}

// ---------------- launch ----------------
extern "C" void kernel_launch(void* const* d_in, const int* in_sizes, int n_in,
                              void* d_out, int out_size)
{
    const float* x    = (const float*)d_in[0];
    const float* w    = (const float*)d_in[1];
    const float* bias = (const float*)d_in[2];
    const float* mult = (const float*)d_in[3];
    float*       out  = (float*)d_out;

    cudaFuncSetAttribute(conv_mma_kernel,
                         cudaFuncAttributeMaxDynamicSharedMemorySize, SMEMB);

    wtrans_kernel<<<(9 * COUT * CIN + 255) / 256, 256>>>(w);
    xtrans_kernel<<<dim3(WW / 32, CIN / 32, BB * HH), dim3(32, 8)>>>(x);
    conv_mma_kernel<<<dim3(OHH, BB), 256, SMEMB>>>(bias, mult, out);
}

// round 12
// speedup vs baseline: 6.3057x; 1.1551x over previous
#include <cuda_runtime.h>
#include <cuda_fp16.h>
#include <cstdint>

// ---------------- problem constants ----------------
#define BB    32
#define CIN   64
#define HH    128
#define WW    128
#define COUT  128
#define OHH   126
#define OWW   126

// ---------------- staging ----------------
// stage = (ki, ci-half): A = 3 kj x 128 co x 32 k halves (24576B),
//                        B = 130 px rows x 32 k halves (64B rows, 132 alloc = 8448B)
#define A_BYTES 24576
#define B_BYTES 8448
#define STAGEB  (A_BYTES + B_BYTES)    // 33024
#define NSTAGE  6
#define SMEMB   (3 * STAGEB)           // 99072, triple-buffered

// static scratch (allocation-free rule); fp16, k-interleaved for fragment loads
__device__ __align__(16) __half g_xTh[(size_t)BB*HH*WW*CIN + 8192]; // [b][h][w][perm(ci)]
__device__ __align__(16) __half g_w2h[9*COUT*CIN];                  // [kk][co][perm(ci)]

// ---------------- helpers ----------------
__device__ __forceinline__ uint32_t smem_u32(const void* p) {
    uint32_t a;
    asm("{ .reg .u64 t; cvta.to.shared.u64 t, %1; cvt.u32.u64 %0, t; }" : "=r"(a) : "l"(p));
    return a;
}
__device__ __forceinline__ void cp16(uint32_t s, const void* g) {
    asm volatile("cp.async.cg.shared.global [%0], [%1], 16;" :: "r"(s), "l"(g));
}
// k-interleave within a 16-group: order [0,1,8,9, 2,3,10,11, 4,5,12,13, 6,7,14,15]
__device__ __forceinline__ int permk(int k) {
    return (((k >> 1) & 3) << 2) | (((k >> 3) & 1) << 1) | (k & 1);
}
__device__ __forceinline__ void mma_f16(float* d, const uint32_t* a, const uint32_t* b) {
    asm volatile(
        "mma.sync.aligned.m16n8k16.row.col.f32.f16.f16.f32 "
        "{%0,%1,%2,%3}, {%4,%5,%6,%7}, {%8,%9}, {%0,%1,%2,%3};"
        : "+f"(d[0]), "+f"(d[1]), "+f"(d[2]), "+f"(d[3])
        : "r"(a[0]), "r"(a[1]), "r"(a[2]), "r"(a[3]), "r"(b[0]), "r"(b[1]));
}

// ---------------- pre-pass: w[co][ci][3][3] -> g_w2h[kk][co][perm(ci)] ----------------
__global__ void wtrans_kernel(const float* __restrict__ w) {
    int idx = blockIdx.x * 256 + threadIdx.x;
    if (idx >= 9 * COUT * CIN) return;
    int ci = idx & 63; int t = idx >> 6; int co = t & 127; int kk = t >> 7;
    int q = (ci & ~15) | permk(ci & 15);
    g_w2h[((size_t)kk * COUT + co) * CIN + q] =
        __float2half_rn(w[((size_t)co * CIN + ci) * 9 + kk]);
}

// ---------------- pre-pass: x[b][ci][h][w] -> g_xTh[b][h][w][perm(ci)] ----------------
__global__ void xtrans_kernel(const float* __restrict__ x) {
    __shared__ float tile[32][33];
    int bh = blockIdx.z;                    // b*128 + h
    int c0 = blockIdx.y * 32;
    int w0 = blockIdx.x * 32;
    int b = bh >> 7, h = bh & 127;
    int tx = threadIdx.x, ty = threadIdx.y; // 32 x 8
    const float* xp = x + ((size_t)b * CIN) * HH * WW + (size_t)h * WW;
#pragma unroll
    for (int i = 0; i < 32; i += 8)
        tile[ty + i][tx] = xp[(size_t)(c0 + ty + i) * HH * WW + w0 + tx];
    __syncthreads();
    __half* xo = g_xTh + (((size_t)b * HH + h) * WW) * CIN;
    int ci = c0 + tx;
    int q = (ci & ~15) | permk(ci & 15);
#pragma unroll
    for (int i = 0; i < 32; i += 8)
        xo[(size_t)(w0 + ty + i) * CIN + q] = __float2half_rn(tile[tx][ty + i]);
}

// ---------------- fused activation ----------------
__device__ __forceinline__ float actf(float v, float bi, float mu) {
    float y = (v + bi) * mu;
    y = (y >= 0.f) ? y : 0.01f * y;
    float t = 0.7978845608028654f * fmaf(0.044715f * y, y * y, y);
    float a = fminf(fabsf(t), 14.f);
    float u = __expf(-2.f * a);                  // (0, 1]
    float th = __fdividef(1.f - u, 1.f + u);     // tanh(a)
    th = (t >= 0.f) ? th : -th;
    return 0.5f * y * (1.f + th);
}

// ---------------- main kernel: implicit GEMM via mma.sync f16 ----------------
// CTA = (oh, b). D[co=128][px=128]; 8 warps in 4(M) x 2(N), each 32x64.
// 6 stages (ki, ci-half), triple-buffered, ONE __syncthreads per stage.
__global__ __launch_bounds__(256, 2)
void conv_mma_kernel(const float* __restrict__ bias, const float* __restrict__ mult,
                     float* __restrict__ out)
{
    extern __shared__ char sm[];
    const int tid = threadIdx.x;
    const int wid = tid >> 5, lid = tid & 31;
    const int wm  = wid >> 1, wn = wid & 1;
    const int g   = lid >> 2, c = lid & 3;
    const int oh  = blockIdx.x;
    const int b   = blockIdx.y;
    const uint32_t sb = smem_u32(sm);

    float acc[2][8][4];
#pragma unroll
    for (int mt = 0; mt < 2; mt++)
#pragma unroll
        for (int nt = 0; nt < 8; nt++)
#pragma unroll
            for (int i = 0; i < 4; i++) acc[mt][nt][i] = 0.f;

    // A rows r = kj*128 + co (384 rows), B rows p = 0..129 (reads past row end feed
    // only masked output pixels 126/127; g_xTh padding covers the final rows).
    // 16B-block rotation (blk+row)&3 keeps LDS.64 fragment loads conflict-free.
#define PREFETCH(S, BOFF) do {                                                  \
        const int ki_ = (S) >> 1, c2_ = (S) & 1;                                \
        const __half* wbase = g_w2h + (size_t)(ki_ * 3) * COUT * CIN + c2_ * 32;\
        const __half* xbase = g_xTh +                                           \
            (((size_t)b * HH + oh + ki_) * WW) * CIN + c2_ * 32;                \
        const uint32_t sbase = sb + (BOFF);                                     \
        _Pragma("unroll")                                                       \
        for (int kq = 0; kq < 9; kq++) {                                        \
            int idx = tid + kq * 256;                                           \
            if (idx < 1536) {                                                   \
                int r = idx >> 2, blk = idx & 3;                                \
                cp16(sbase + r * 64 + ((blk + r) & 3) * 16,                     \
                     wbase + (size_t)r * CIN + blk * 8);                        \
            } else if (idx < 2056) {                                            \
                int j = idx - 1536, p = j >> 2, blk = j & 3;                    \
                cp16(sbase + A_BYTES + p * 64 + ((blk + p) & 3) * 16,           \
                     xbase + (size_t)p * CIN + blk * 8);                        \
            }                                                                   \
        }                                                                       \
        asm volatile("cp.async.commit_group;" ::: "memory");                    \
    } while (0)
    // note: A row r spans [kj][co] with stride CIN -> wbase + r*CIN covers all 3 kj

    PREFETCH(0, 0);
    PREFETCH(1, STAGEB);

    int coff = 0;                 // buffer offset of stage s
    int poff = 2 * STAGEB;        // buffer offset of stage s+2
#pragma unroll 1
    for (int s = 0; s < NSTAGE; s++) {
        if (s < NSTAGE - 1) asm volatile("cp.async.wait_group 1;" ::: "memory");
        else                asm volatile("cp.async.wait_group 0;" ::: "memory");
        __syncthreads();
        if (s + 2 < NSTAGE) PREFETCH(s + 2, poff);

        const uint32_t Ab = sb + coff;
        const uint32_t Bb = Ab + A_BYTES;
        const int s8 = (c & 1) * 8;

#pragma unroll
        for (int kj = 0; kj < 3; kj++) {
#pragma unroll
            for (int ks = 0; ks < 2; ks++) {
                const int blk = ks * 2 + (c >> 1);
                uint32_t af[2][4];
#pragma unroll
                for (int mt = 0; mt < 2; mt++) {
                    int r0 = kj * 128 + wm * 32 + mt * 16 + g;
                    uint32_t a0 = Ab + r0 * 64 + ((blk + r0) & 3) * 16 + s8;
                    uint32_t a1 = Ab + (r0 + 8) * 64 + ((blk + r0 + 8) & 3) * 16 + s8;
                    asm volatile("ld.shared.v2.b32 {%0,%1}, [%2];"
                                 : "=r"(af[mt][0]), "=r"(af[mt][2]) : "r"(a0));
                    asm volatile("ld.shared.v2.b32 {%0,%1}, [%2];"
                                 : "=r"(af[mt][1]), "=r"(af[mt][3]) : "r"(a1));
                }
                uint32_t bf[8][2];
#pragma unroll
                for (int nt = 0; nt < 8; nt++) {
                    int n = wn * 64 + nt * 8 + g + kj;
                    uint32_t a = Bb + n * 64 + ((blk + n) & 3) * 16 + s8;
                    asm volatile("ld.shared.v2.b32 {%0,%1}, [%2];"
                                 : "=r"(bf[nt][0]), "=r"(bf[nt][1]) : "r"(a));
                }
#pragma unroll
                for (int mt = 0; mt < 2; mt++)
#pragma unroll
                    for (int nt = 0; nt < 8; nt++)
                        mma_f16(acc[mt][nt], af[mt], bf[nt]);
            }
        }
        coff += STAGEB; if (coff == 3 * STAGEB) coff = 0;
        poff += STAGEB; if (poff == 3 * STAGEB) poff = 0;
    }

    // ---- epilogue: bias -> mult -> leaky -> GELU -> store ----
#pragma unroll
    for (int mt = 0; mt < 2; mt++) {
#pragma unroll
        for (int half = 0; half < 2; half++) {
            const int co = wm * 32 + mt * 16 + g + half * 8;
            const float bi = bias[co];
            const float mu = mult[co];
            float* op = out + (((size_t)b * COUT + co) * OHH + oh) * OWW;
#pragma unroll
            for (int nt = 0; nt < 8; nt++) {
                const int ow = wn * 64 + nt * 8 + 2 * c;
                if (ow + 1 < OWW) {
                    float f0 = actf(acc[mt][nt][half * 2 + 0], bi, mu);
                    float f1 = actf(acc[mt][nt][half * 2 + 1], bi, mu);
                    *reinterpret_cast<float2*>(op + ow) = make_float2(f0, f1);
                }
            }
        }
    }
}

// ---------------- launch ----------------
extern "C" void kernel_launch(void* const* d_in, const int* in_sizes, int n_in,
                              void* d_out, int out_size)
{
    const float* x    = (const float*)d_in[0];
    const float* w    = (const float*)d_in[1];
    const float* bias = (const float*)d_in[2];
    const float* mult = (const float*)d_in[3];
    float*       out  = (float*)d_out;

    cudaFuncSetAttribute(conv_mma_kernel,
                         cudaFuncAttributeMaxDynamicSharedMemorySize, SMEMB);

    wtrans_kernel<<<(9 * COUT * CIN + 255) / 256, 256>>>(w);
    xtrans_kernel<<<dim3(WW / 32, CIN / 32, BB * HH), dim3(32, 8)>>>(x);
    conv_mma_kernel<<<dim3(OHH, BB), 256, SMEMB>>>(bias, mult, out);
}